// round 9
// baseline (speedup 1.0000x reference)
#include <cuda_runtime.h>
#include <cuda_bf16.h>
#include <cstdint>

typedef unsigned long long ull;

#define SQ   4096
#define DIM  768
#define HID  384
#define G4   1536
#define NEV  1024

// ---------------- static scratch (no runtime allocation) ----------------
__device__ float g_xw[2u * SQ * G4];    // permuted gate preactivations, both dirs
__device__ float g_tok[(size_t)SQ * DIM];
__device__ float g_emb[NEV * DIM];
__device__ float g_hidn[NEV * DIM];
__device__ float g_evloss[NEV];
__device__ float g_scores_scratch[2 * NEV];
__device__ float g_loss_scratch[1];

// accuracy-safe fast activations (validated at rel_err 4e-6 in R5;
// MUFU tanh.approx was exonerated by R8 but keep the validated versions)
__device__ __forceinline__ float fast_sig(float x) {
    return __fdividef(1.0f, 1.0f + __expf(-x));
}
__device__ __forceinline__ float fast_tanh(float x) {
    return 1.0f - __fdividef(2.0f, __expf(2.0f * x) + 1.0f);
}

__device__ __forceinline__ unsigned smem_u32(const void* p) {
    unsigned a;
    asm("{ .reg .u64 t; cvta.to.shared.u64 t, %1; cvt.u32.u64 %0, t; }" : "=r"(a) : "l"(p));
    return a;
}

__device__ __forceinline__ void mbar_wait(unsigned mbar, unsigned parity) {
    unsigned done;
    asm volatile("{\n\t.reg .pred p;\n\t"
        "mbarrier.try_wait.parity.acquire.cluster.shared::cta.b64 p, [%1], %2;\n\t"
        "selp.b32 %0, 1, 0, p;\n\t}"
        : "=r"(done) : "r"(mbar), "r"(parity) : "memory");
    while (!done) {
        asm volatile("{\n\t.reg .pred p;\n\t"
            "mbarrier.try_wait.parity.acquire.cluster.shared::cta.b64 p, [%1], %2, 0x989680;\n\t"
            "selp.b32 %0, 1, 0, p;\n\t}"
            : "=r"(done) : "r"(mbar), "r"(parity) : "memory");
    }
}

__device__ __forceinline__ void mbar_expect(unsigned mbar, unsigned bytes) {
    asm volatile("mbarrier.arrive.expect_tx.shared.b64 _, [%0], %1;"
                 :: "r"(mbar), "r"(bytes) : "memory");
}

// ---------------------------------------------------------------------------
// GEMM A: xw[d][t][jj] = X[t] . W_d[orig(jj)] + (bih+bhh)[orig]
// column permutation: jj = cta*96 + gate*24 + u  <->  orig = gate*384 + cta*24 + u
// ---------------------------------------------------------------------------
__global__ __launch_bounds__(256) void gemm_xw_kernel(
    const float* __restrict__ X,
    const float* __restrict__ Wf, const float* __restrict__ Wb,
    const float* __restrict__ bihf, const float* __restrict__ bhhf,
    const float* __restrict__ bihb, const float* __restrict__ bhhb)
{
    __shared__ float As[32][72];
    __shared__ float Bs[32][72];
    __shared__ const float* wptr[64];
    __shared__ float biasv[64];

    int tid = threadIdx.x;
    int bx = blockIdx.x, by = blockIdx.y;

    if (tid < 64) {
        int jp = bx * 64 + tid;          // 0..3071
        int d  = jp / G4;
        int jj = jp - d * G4;
        int cc = jj / 96, ll = jj % 96;
        int orig = (ll / 24) * HID + cc * 24 + (ll % 24);
        wptr[tid]  = (d ? Wb : Wf) + (size_t)orig * DIM;
        biasv[tid] = d ? (bihb[orig] + bhhb[orig]) : (bihf[orig] + bhhf[orig]);
    }
    __syncthreads();

    int tx = tid & 15, ty = tid >> 4;
    ull acc2[4][2];
    #pragma unroll
    for (int i = 0; i < 4; i++) { acc2[i][0] = 0ull; acc2[i][1] = 0ull; }

    for (int k0 = 0; k0 < DIM; k0 += 32) {
        #pragma unroll
        for (int i = 0; i < 2; i++) {
            int id = tid + i * 256;
            int r = id >> 3, c4 = id & 7;
            float4 v = *reinterpret_cast<const float4*>(X + (size_t)(by * 64 + r) * DIM + k0 + c4 * 4);
            As[c4*4+0][r] = v.x; As[c4*4+1][r] = v.y; As[c4*4+2][r] = v.z; As[c4*4+3][r] = v.w;
            float4 w = *reinterpret_cast<const float4*>(wptr[r] + k0 + c4 * 4);
            Bs[c4*4+0][r] = w.x; Bs[c4*4+1][r] = w.y; Bs[c4*4+2][r] = w.z; Bs[c4*4+3][r] = w.w;
        }
        __syncthreads();
        #pragma unroll
        for (int k = 0; k < 32; k++) {
            float4 av = *reinterpret_cast<const float4*>(&As[k][ty * 4]);
            ull b0 = *reinterpret_cast<const ull*>(&Bs[k][tx * 4]);
            ull b1 = *reinterpret_cast<const ull*>(&Bs[k][tx * 4 + 2]);
            float a_[4] = {av.x, av.y, av.z, av.w};
            #pragma unroll
            for (int i = 0; i < 4; i++) {
                ull ad;
                asm("mov.b64 %0, {%1, %1};" : "=l"(ad) : "f"(a_[i]));
                asm("fma.rn.f32x2 %0, %1, %2, %0;" : "+l"(acc2[i][0]) : "l"(ad), "l"(b0));
                asm("fma.rn.f32x2 %0, %1, %2, %0;" : "+l"(acc2[i][1]) : "l"(ad), "l"(b1));
            }
        }
        __syncthreads();
    }

    int d = (bx * 64) / G4;
    size_t outbase = (size_t)d * SQ * G4;
    int col0 = bx * 64 - d * G4 + tx * 4;
    #pragma unroll
    for (int i = 0; i < 4; i++) {
        int t = by * 64 + ty * 4 + i;
        float2 p0 = *reinterpret_cast<float2*>(&acc2[i][0]);
        float2 p1 = *reinterpret_cast<float2*>(&acc2[i][1]);
        float* o = g_xw + outbase + (size_t)t * G4 + col0;
        o[0] = p0.x + biasv[tx*4+0];
        o[1] = p0.y + biasv[tx*4+1];
        o[2] = p1.x + biasv[tx*4+2];
        o[3] = p1.y + biasv[tx*4+3];
    }
}

// ---------------------------------------------------------------------------
// LSTM: one 16-CTA cluster per direction. Weights register-resident.
// Thread roles: tid = u*16 + p  (u = unit 0..23, p = 0..15; g = p>>2, q = p&3).
//   MAC: row g*24+u, k-chunk q (96 of 384 h). Gate exchange is warp-internal
//   (units 2w, 2w+1 live in warp w): butterfly over q, then 4 shfl.idx to
//   gather the gates; activation replicated across the 16 p-lanes of a unit.
// h exchange: 24 hv staged contiguously in SMEM (parity-double-buffered),
// then 16 threads each issue ONE cp.async.bulk (96 B) to a peer's h buffer
// with remote-mbarrier complete_tx -> 16 tx events/step/CTA instead of 384.
// R8 bug fixed here: bulk SOURCE is sh_stage[par] (the staging written THIS
// step); dst/rmb target the NEXT buffer (1-par). Staging-reuse is safe: my
// t+2 wait on mb[par] requires all peers' t+1 bulks, which require their
// receipt of all my step-t bulks (the only readers of sh_stage[par]).
// ---------------------------------------------------------------------------
__global__ __launch_bounds__(384, 1) void lstm_kernel(
    const float* __restrict__ Whh_f, const float* __restrict__ Whh_b)
{
    __shared__ __align__(16) float sh_h[2 * 400];    // [buf][chunk q at q*100]
    __shared__ __align__(16) float sh_stage[2][24];  // outgoing hv, by parity
    __shared__ __align__(8) ull sh_mbar[2];

    int tid = threadIdx.x;
    int dir = blockIdx.x >> 4;
    unsigned cta;
    asm("mov.u32 %0, %%cluster_ctarank;" : "=r"(cta));

    int u = tid >> 4, p = tid & 15;
    int g = p >> 2, q = p & 3;
    int orig = g * HID + (int)cta * 24 + u;

    const float* Whh = dir ? Whh_b : Whh_f;
    const ull* wrow = reinterpret_cast<const ull*>(Whh + (size_t)orig * HID + q * 96);
    ull wreg[48];
    #pragma unroll
    for (int j = 0; j < 48; j++) wreg[j] = wrow[j];

    // zero both h buffers
    for (int i = tid; i < 2 * 400; i += 384) sh_h[i] = 0.0f;

    unsigned mb0 = smem_u32(&sh_mbar[0]);
    unsigned mb1 = mb0 + 8;
    if (tid == 0) {
        asm volatile("mbarrier.init.shared.b64 [%0], 1;" :: "r"(mb0) : "memory");
        asm volatile("mbarrier.init.shared.b64 [%0], 1;" :: "r"(mb1) : "memory");
        mbar_expect(mb0, 1536);
        mbar_expect(mb1, 1536);
        asm volatile("fence.mbarrier_init.release.cluster;" ::: "memory");
    }
    __syncthreads();

    // bulk-issuer setup (threads 0..15, issuer's destination peer P = tid)
    unsigned dst0 = 0, dst1 = 0, rmb0 = 0, rmb1 = 0, src0 = 0, src1 = 0;
    if (tid < 16) {
        unsigned P = tid;
        // my 24-float run lands at chunk cta/4, offset (cta%4)*24 (fully inside one chunk)
        unsigned off = ((cta >> 2) * 100 + (cta & 3) * 24) * 4;
        unsigned l0 = smem_u32(sh_h) + off;            // buf0
        unsigned l1 = l0 + 400 * 4;                    // buf1
        asm("mapa.shared::cluster.u32 %0, %1, %2;" : "=r"(dst0) : "r"(l0), "r"(P));
        asm("mapa.shared::cluster.u32 %0, %1, %2;" : "=r"(dst1) : "r"(l1), "r"(P));
        asm("mapa.shared::cluster.u32 %0, %1, %2;" : "=r"(rmb0) : "r"(mb0), "r"(P));
        asm("mapa.shared::cluster.u32 %0, %1, %2;" : "=r"(rmb1) : "r"(mb1), "r"(P));
        src0 = smem_u32(&sh_stage[0][0]);
        src1 = smem_u32(&sh_stage[1][0]);
    }

    // all buffers zeroed + mbarriers initialized cluster-wide
    asm volatile("barrier.cluster.arrive.aligned;" ::: "memory");
    asm volatile("barrier.cluster.wait.aligned;"   ::: "memory");

    const float* xwp = g_xw + (size_t)dir * SQ * G4 + (size_t)cta * 96 + (g * 24 + u);
    float c_reg = 0.0f;
    float xw_cur = __ldcg(xwp + (size_t)(dir ? SQ - 1 : 0) * G4);
    unsigned ph0 = 0, ph1 = 0;
    int lane = tid & 31;
    int gbase = (lane & 16) | q;     // lane of (this unit, gate 0, my q)
    int hidx = (int)cta * 24 + u;

    for (int t = 0; t < SQ; t++) {
        int par = t & 1;

        // prefetch next step's xw before the wait
        float xw_next = 0.0f;
        if (t + 1 < SQ) {
            int tn = dir ? (SQ - 2 - t) : (t + 1);
            xw_next = __ldcg(xwp + (size_t)tn * G4);
        }

        // wait for this step's h buffer (t=0 consumes zeros)
        if (t > 0) {
            if (par) { mbar_wait(mb1, ph1); ph1 ^= 1; if (tid == 0) mbar_expect(mb1, 1536); }
            else     { mbar_wait(mb0, ph0); ph0 ^= 1; if (tid == 0) mbar_expect(mb0, 1536); }
        }

        // MAC: row (g*24+u), k-chunk q
        const ulonglong2* hp2 =
            reinterpret_cast<const ulonglong2*>(sh_h + par * 400 + q * 100);
        ull a0 = 0ull, a1 = 0ull, a2 = 0ull, a3 = 0ull;
        #pragma unroll
        for (int j = 0; j < 12; j++) {
            ulonglong2 x0 = hp2[2 * j];
            ulonglong2 x1 = hp2[2 * j + 1];
            asm("fma.rn.f32x2 %0, %1, %2, %0;" : "+l"(a0) : "l"(wreg[4*j+0]), "l"(x0.x));
            asm("fma.rn.f32x2 %0, %1, %2, %0;" : "+l"(a1) : "l"(wreg[4*j+1]), "l"(x0.y));
            asm("fma.rn.f32x2 %0, %1, %2, %0;" : "+l"(a2) : "l"(wreg[4*j+2]), "l"(x1.x));
            asm("fma.rn.f32x2 %0, %1, %2, %0;" : "+l"(a3) : "l"(wreg[4*j+3]), "l"(x1.y));
        }
        asm("add.rn.f32x2 %0, %0, %1;" : "+l"(a0) : "l"(a1));
        asm("add.rn.f32x2 %0, %0, %1;" : "+l"(a2) : "l"(a3));
        asm("add.rn.f32x2 %0, %0, %1;" : "+l"(a0) : "l"(a2));
        float lo, hi;
        asm("mov.b64 {%0, %1}, %2;" : "=f"(lo), "=f"(hi) : "l"(a0));
        float s = lo + hi;
        if (q == 0) s += xw_cur;            // add xw once per row
        s += __shfl_xor_sync(0xffffffffu, s, 1);
        s += __shfl_xor_sync(0xffffffffu, s, 2);   // all 4 q-lanes: full row sum

        // gather the 4 gate sums of my unit (warp-internal)
        float gi = __shfl_sync(0xffffffffu, s, gbase + 0);
        float gf = __shfl_sync(0xffffffffu, s, gbase + 4);
        float gg = __shfl_sync(0xffffffffu, s, gbase + 8);
        float go = __shfl_sync(0xffffffffu, s, gbase + 12);

        // activation (replicated across the 16 p-lanes, deterministic)
        float cf = fast_sig(gf) * c_reg + fast_sig(gi) * fast_tanh(gg);
        c_reg = cf;
        float hv = fast_sig(go) * fast_tanh(cf);

        if (p == 0) sh_stage[par][u] = hv;
        if (p == 1) {
            int tt = dir ? (SQ - 1 - t) : t;
            g_tok[(size_t)tt * DIM + dir * HID + hidx] = hv;
        }

        __syncthreads();   // staging visible + all h reads done before any bulk

        if (tid < 16 && t + 1 < SQ) {
            asm volatile("fence.proxy.async.shared::cta;" ::: "memory");
            unsigned dst = par ? dst0 : dst1;      // next buffer (1-par)
            unsigned rmb = par ? rmb0 : rmb1;      // its mbarrier
            unsigned src = par ? src1 : src0;      // FIXED: staging written THIS step
            asm volatile(
                "cp.async.bulk.shared::cluster.shared::cta.mbarrier::complete_tx::bytes "
                "[%0], [%1], 96, [%2];"
                :: "r"(dst), "r"(src), "r"(rmb) : "memory");
        }

        xw_cur = xw_next;
    }

    // keep SMEM alive until all cluster CTAs are done
    asm volatile("barrier.cluster.arrive.aligned;" ::: "memory");
    asm volatile("barrier.cluster.wait.aligned;"   ::: "memory");
}

// ---------------------------------------------------------------------------
// Event mean-pool: one CTA per event
// ---------------------------------------------------------------------------
__global__ __launch_bounds__(256) void pool_kernel(const int* __restrict__ label_event)
{
    int e = blockIdx.x;
    int start = label_event[e * 3 + 0];
    int end   = label_event[e * 3 + 1];
    float inv = 1.0f / (float)(end - start);
    for (int c = threadIdx.x; c < DIM; c += 256) {
        float s = 0.0f;
        for (int r = start; r < end; r++) s += g_tok[(size_t)r * DIM + c];
        g_emb[(size_t)e * DIM + c] = s * inv;
    }
}

// ---------------------------------------------------------------------------
// MLP layer 1: hid = relu(emb @ W1^T + b1)   [1024 x 768] x [768 x 768]
// ---------------------------------------------------------------------------
__global__ __launch_bounds__(256) void gemm_mlp1_kernel(
    const float* __restrict__ W1, const float* __restrict__ b1)
{
    __shared__ float As[32][72];
    __shared__ float Bs[32][72];

    int tid = threadIdx.x;
    int bx = blockIdx.x, by = blockIdx.y;
    int tx = tid & 15, ty = tid >> 4;

    ull acc2[4][2];
    #pragma unroll
    for (int i = 0; i < 4; i++) { acc2[i][0] = 0ull; acc2[i][1] = 0ull; }

    for (int k0 = 0; k0 < DIM; k0 += 32) {
        #pragma unroll
        for (int i = 0; i < 2; i++) {
            int id = tid + i * 256;
            int r = id >> 3, c4 = id & 7;
            float4 v = *reinterpret_cast<const float4*>(g_emb + (size_t)(by * 64 + r) * DIM + k0 + c4 * 4);
            As[c4*4+0][r] = v.x; As[c4*4+1][r] = v.y; As[c4*4+2][r] = v.z; As[c4*4+3][r] = v.w;
            float4 w = *reinterpret_cast<const float4*>(W1 + (size_t)(bx * 64 + r) * DIM + k0 + c4 * 4);
            Bs[c4*4+0][r] = w.x; Bs[c4*4+1][r] = w.y; Bs[c4*4+2][r] = w.z; Bs[c4*4+3][r] = w.w;
        }
        __syncthreads();
        #pragma unroll
        for (int k = 0; k < 32; k++) {
            float4 av = *reinterpret_cast<const float4*>(&As[k][ty * 4]);
            ull b0 = *reinterpret_cast<const ull*>(&Bs[k][tx * 4]);
            ull b1v = *reinterpret_cast<const ull*>(&Bs[k][tx * 4 + 2]);
            float a_[4] = {av.x, av.y, av.z, av.w};
            #pragma unroll
            for (int i = 0; i < 4; i++) {
                ull ad;
                asm("mov.b64 %0, {%1, %1};" : "=l"(ad) : "f"(a_[i]));
                asm("fma.rn.f32x2 %0, %1, %2, %0;" : "+l"(acc2[i][0]) : "l"(ad), "l"(b0));
                asm("fma.rn.f32x2 %0, %1, %2, %0;" : "+l"(acc2[i][1]) : "l"(ad), "l"(b1v));
            }
        }
        __syncthreads();
    }

    int col0 = bx * 64 + tx * 4;
    #pragma unroll
    for (int i = 0; i < 4; i++) {
        int row = by * 64 + ty * 4 + i;
        float2 p0 = *reinterpret_cast<float2*>(&acc2[i][0]);
        float2 p1 = *reinterpret_cast<float2*>(&acc2[i][1]);
        float* o = g_hidn + (size_t)row * DIM + col0;
        o[0] = fmaxf(p0.x + b1[col0 + 0], 0.0f);
        o[1] = fmaxf(p0.y + b1[col0 + 1], 0.0f);
        o[2] = fmaxf(p1.x + b1[col0 + 2], 0.0f);
        o[3] = fmaxf(p1.y + b1[col0 + 3], 0.0f);
    }
}

// ---------------------------------------------------------------------------
// Layer 2 + log-softmax + weighted CE per event. One warp per event.
// ---------------------------------------------------------------------------
__global__ __launch_bounds__(256) void scores_kernel(
    const float* __restrict__ W2, const float* __restrict__ b2,
    const int* __restrict__ label_event, float* scores_out)
{
    int lane = threadIdx.x & 31;
    int w = threadIdx.x >> 5;
    int e = blockIdx.x * 8 + w;
    const float* hrow = g_hidn + (size_t)e * DIM;

    float s0 = 0.0f, s1 = 0.0f;
    #pragma unroll
    for (int k = 0; k < 24; k++) {
        float v = hrow[lane + 32 * k];
        s0 += v * __ldg(&W2[lane + 32 * k]);
        s1 += v * __ldg(&W2[DIM + lane + 32 * k]);
    }
    #pragma unroll
    for (int m = 16; m >= 1; m >>= 1) {
        s0 += __shfl_xor_sync(0xffffffffu, s0, m);
        s1 += __shfl_xor_sync(0xffffffffu, s1, m);
    }
    if (lane == 0) {
        s0 += b2[0]; s1 += b2[1];
        float* sp = scores_out ? scores_out : g_scores_scratch;
        sp[2 * e + 0] = s0;
        sp[2 * e + 1] = s1;
        float mx = fmaxf(s0, s1);
        float lse = mx + logf(expf(s0 - mx) + expf(s1 - mx));
        int lab = label_event[e * 3 + 2];
        float sl = lab ? s1 : s0;
        float ce = lse - sl;
        float wgt = (lab == 0) ? 1.0f : (float)lab * 1.0f;
        g_evloss[e] = ce * wgt;
    }
}

__global__ __launch_bounds__(1024) void loss_reduce_kernel(float* loss_out)
{
    __shared__ float red[1024];
    int tid = threadIdx.x;
    red[tid] = g_evloss[tid];
    __syncthreads();
    for (int s = 512; s >= 1; s >>= 1) {
        if (tid < s) red[tid] += red[tid + s];
        __syncthreads();
    }
    if (tid == 0) {
        float* lp = loss_out ? loss_out : g_loss_scratch;
        lp[0] = red[0];
    }
}

// ---------------------------------------------------------------------------
extern "C" void kernel_launch(void* const* d_in, const int* in_sizes, int n_in,
                              void* d_out, int out_size) {
    const float* X     = (const float*)d_in[0];
    const int*   lev   = (const int*)  d_in[1];
    const float* Wih_f = (const float*)d_in[2];
    const float* Whh_f = (const float*)d_in[3];
    const float* bih_f = (const float*)d_in[4];
    const float* bhh_f = (const float*)d_in[5];
    const float* Wih_b = (const float*)d_in[6];
    const float* Whh_b = (const float*)d_in[7];
    const float* bih_b = (const float*)d_in[8];
    const float* bhh_b = (const float*)d_in[9];
    const float* W1    = (const float*)d_in[10];
    const float* b1    = (const float*)d_in[11];
    const float* W2    = (const float*)d_in[12];
    const float* b2    = (const float*)d_in[13];

    float* out = (float*)d_out;
    float* loss_ptr   = nullptr;
    float* scores_ptr = nullptr;
    if (out_size >= 2049)      { loss_ptr = out; scores_ptr = out + 1; }
    else if (out_size >= 2048) { scores_ptr = out; }
    else                       { loss_ptr = out; }

    gemm_xw_kernel<<<dim3(48, 64), 256>>>(X, Wih_f, Wih_b, bih_f, bhh_f, bih_b, bhh_b);

    // LSTM: 2 clusters of 16 CTAs (non-portable cluster size)
    cudaFuncSetAttribute((const void*)lstm_kernel,
                         cudaFuncAttributeNonPortableClusterSizeAllowed, 1);
    cudaLaunchConfig_t cfg = {};
    cfg.gridDim  = dim3(32, 1, 1);
    cfg.blockDim = dim3(384, 1, 1);
    cfg.dynamicSmemBytes = 0;
    cudaLaunchAttribute attrs[1];
    attrs[0].id = cudaLaunchAttributeClusterDimension;
    attrs[0].val.clusterDim.x = 16;
    attrs[0].val.clusterDim.y = 1;
    attrs[0].val.clusterDim.z = 1;
    cfg.attrs = attrs;
    cfg.numAttrs = 1;
    cudaLaunchKernelEx(&cfg, lstm_kernel, Whh_f, Whh_b);

    pool_kernel<<<NEV, 256>>>(lev);
    gemm_mlp1_kernel<<<dim3(12, 16), 256>>>(W1, b1);
    scores_kernel<<<NEV / 8, 256>>>(W2, b2, lev, scores_ptr);
    loss_reduce_kernel<<<1, 1024>>>(loss_ptr);
}

// round 13
// speedup vs baseline: 1.0271x; 1.0271x over previous
#include <cuda_runtime.h>
#include <cuda_bf16.h>
#include <cstdint>

typedef unsigned long long ull;

#define SQ   4096
#define DIM  768
#define HID  384
#define G4   1536
#define NEV  1024

// ---------------- static scratch (no runtime allocation) ----------------
__device__ float g_xw[2u * SQ * G4];    // permuted gate preactivations, both dirs
__device__ float g_tok[(size_t)SQ * DIM];
__device__ float g_emb[NEV * DIM];
__device__ float g_hidn[NEV * DIM];
__device__ float g_evloss[NEV];
__device__ float g_scores_scratch[2 * NEV];
__device__ float g_loss_scratch[1];

// accuracy-safe fast activations (validated at rel_err 4e-6)
__device__ __forceinline__ float fast_sig(float x) {
    return __fdividef(1.0f, 1.0f + __expf(-x));
}
__device__ __forceinline__ float fast_tanh(float x) {
    return 1.0f - __fdividef(2.0f, __expf(2.0f * x) + 1.0f);
}

__device__ __forceinline__ unsigned smem_u32(const void* p) {
    unsigned a;
    asm("{ .reg .u64 t; cvta.to.shared.u64 t, %1; cvt.u32.u64 %0, t; }" : "=r"(a) : "l"(p));
    return a;
}

__device__ __forceinline__ void mbar_wait(unsigned mbar, unsigned parity) {
    unsigned done;
    asm volatile("{\n\t.reg .pred p;\n\t"
        "mbarrier.try_wait.parity.acquire.cluster.shared::cta.b64 p, [%1], %2;\n\t"
        "selp.b32 %0, 1, 0, p;\n\t}"
        : "=r"(done) : "r"(mbar), "r"(parity) : "memory");
    while (!done) {
        asm volatile("{\n\t.reg .pred p;\n\t"
            "mbarrier.try_wait.parity.acquire.cluster.shared::cta.b64 p, [%1], %2, 0x989680;\n\t"
            "selp.b32 %0, 1, 0, p;\n\t}"
            : "=r"(done) : "r"(mbar), "r"(parity) : "memory");
    }
}

__device__ __forceinline__ void mbar_expect(unsigned mbar, unsigned bytes) {
    asm volatile("mbarrier.arrive.expect_tx.shared.b64 _, [%0], %1;"
                 :: "r"(mbar), "r"(bytes) : "memory");
}

// ---------------------------------------------------------------------------
// GEMM A: xw[d][t][jj] = X[t] . W_d[orig(jj)] + (bih+bhh)[orig]
// column permutation: jj = cta*96 + gate*24 + u  <->  orig = gate*384 + cta*24 + u
// ---------------------------------------------------------------------------
__global__ __launch_bounds__(256) void gemm_xw_kernel(
    const float* __restrict__ X,
    const float* __restrict__ Wf, const float* __restrict__ Wb,
    const float* __restrict__ bihf, const float* __restrict__ bhhf,
    const float* __restrict__ bihb, const float* __restrict__ bhhb)
{
    __shared__ float As[32][72];
    __shared__ float Bs[32][72];
    __shared__ const float* wptr[64];
    __shared__ float biasv[64];

    int tid = threadIdx.x;
    int bx = blockIdx.x, by = blockIdx.y;

    if (tid < 64) {
        int jp = bx * 64 + tid;          // 0..3071
        int d  = jp / G4;
        int jj = jp - d * G4;
        int cc = jj / 96, ll = jj % 96;
        int orig = (ll / 24) * HID + cc * 24 + (ll % 24);
        wptr[tid]  = (d ? Wb : Wf) + (size_t)orig * DIM;
        biasv[tid] = d ? (bihb[orig] + bhhb[orig]) : (bihf[orig] + bhhf[orig]);
    }
    __syncthreads();

    int tx = tid & 15, ty = tid >> 4;
    ull acc2[4][2];
    #pragma unroll
    for (int i = 0; i < 4; i++) { acc2[i][0] = 0ull; acc2[i][1] = 0ull; }

    for (int k0 = 0; k0 < DIM; k0 += 32) {
        #pragma unroll
        for (int i = 0; i < 2; i++) {
            int id = tid + i * 256;
            int r = id >> 3, c4 = id & 7;
            float4 v = *reinterpret_cast<const float4*>(X + (size_t)(by * 64 + r) * DIM + k0 + c4 * 4);
            As[c4*4+0][r] = v.x; As[c4*4+1][r] = v.y; As[c4*4+2][r] = v.z; As[c4*4+3][r] = v.w;
            float4 w = *reinterpret_cast<const float4*>(wptr[r] + k0 + c4 * 4);
            Bs[c4*4+0][r] = w.x; Bs[c4*4+1][r] = w.y; Bs[c4*4+2][r] = w.z; Bs[c4*4+3][r] = w.w;
        }
        __syncthreads();
        #pragma unroll
        for (int k = 0; k < 32; k++) {
            float4 av = *reinterpret_cast<const float4*>(&As[k][ty * 4]);
            ull b0 = *reinterpret_cast<const ull*>(&Bs[k][tx * 4]);
            ull b1 = *reinterpret_cast<const ull*>(&Bs[k][tx * 4 + 2]);
            float a_[4] = {av.x, av.y, av.z, av.w};
            #pragma unroll
            for (int i = 0; i < 4; i++) {
                ull ad;
                asm("mov.b64 %0, {%1, %1};" : "=l"(ad) : "f"(a_[i]));
                asm("fma.rn.f32x2 %0, %1, %2, %0;" : "+l"(acc2[i][0]) : "l"(ad), "l"(b0));
                asm("fma.rn.f32x2 %0, %1, %2, %0;" : "+l"(acc2[i][1]) : "l"(ad), "l"(b1));
            }
        }
        __syncthreads();
    }

    int d = (bx * 64) / G4;
    size_t outbase = (size_t)d * SQ * G4;
    int col0 = bx * 64 - d * G4 + tx * 4;
    #pragma unroll
    for (int i = 0; i < 4; i++) {
        int t = by * 64 + ty * 4 + i;
        float2 p0 = *reinterpret_cast<float2*>(&acc2[i][0]);
        float2 p1 = *reinterpret_cast<float2*>(&acc2[i][1]);
        float* o = g_xw + outbase + (size_t)t * G4 + col0;
        o[0] = p0.x + biasv[tx*4+0];
        o[1] = p0.y + biasv[tx*4+1];
        o[2] = p1.x + biasv[tx*4+2];
        o[3] = p1.y + biasv[tx*4+3];
    }
}

// ---------------------------------------------------------------------------
// LSTM: one 16-CTA cluster per direction. Weights register-resident.
// Thread roles: tid = u*16 + p  (u = unit 0..23, p = 0..15; g = p>>2, q = p&3).
// Gate exchange warp-internal (butterfly + 4 shfl.idx).
// h exchange: direct st.async.b64 (bulk DMA rejected: R9 measured +340ns/step).
//   - 24 hv staged (parity-buffered); 192 issuer threads (P = tid&15,
//     j = tid>>4) each push one 8-byte pair to peer P's next h buffer.
//   - 4 per-chunk mbarriers per parity (chunk = 96-float k-slice; each CTA's
//     24 units land wholly in chunk cta/4). Each chunk mbar expects 384 B =
//     4 source CTAs x 12 b64 = 48 tx events, draining on 4 separate
//     addresses (32 B apart) in parallel.
//   - Each thread waits ONLY its own chunk's mbar (q = p&3); threads 0..3
//     re-arm chunk q after their wait (re-armer is a waiter of that mbar;
//     re-arm precedes __syncthreads precedes my stores, which gate peers'
//     next-phase completes -> no lost-wakeup window).
// Reuse safety: a CTA's __syncthreads at step t requires all 4 chunk waits
// -> union of sources = all 16 CTAs; transitive arguments from R5/R9 hold.
// ---------------------------------------------------------------------------
__global__ __launch_bounds__(384, 1) void lstm_kernel(
    const float* __restrict__ Whh_f, const float* __restrict__ Whh_b)
{
    __shared__ __align__(16) float sh_h[2 * 400];    // [buf][chunk q at q*100]
    __shared__ __align__(16) float sh_stage[2][24];  // outgoing hv, by parity
    __shared__ __align__(8) ull sh_mbar[32];         // mbar (par*4+chunk) at idx*4 (32B apart)

    int tid = threadIdx.x;
    int dir = blockIdx.x >> 4;
    unsigned cta;
    asm("mov.u32 %0, %%cluster_ctarank;" : "=r"(cta));

    int u = tid >> 4, p = tid & 15;
    int g = p >> 2, q = p & 3;
    int orig = g * HID + (int)cta * 24 + u;

    const float* Whh = dir ? Whh_b : Whh_f;
    const ull* wrow = reinterpret_cast<const ull*>(Whh + (size_t)orig * HID + q * 96);
    ull wreg[48];
    #pragma unroll
    for (int j = 0; j < 48; j++) wreg[j] = wrow[j];

    // zero both h buffers
    for (int i = tid; i < 2 * 400; i += 384) sh_h[i] = 0.0f;

    unsigned mbbase = smem_u32(&sh_mbar[0]);
    if (tid == 0) {
        #pragma unroll
        for (int i = 0; i < 8; i++) {
            unsigned mb = mbbase + i * 32;
            asm volatile("mbarrier.init.shared.b64 [%0], 1;" :: "r"(mb) : "memory");
            mbar_expect(mb, 384);
        }
        asm volatile("fence.mbarrier_init.release.cluster;" ::: "memory");
    }
    __syncthreads();

    // issuer setup (threads 0..191): P = tid&15 (dest peer), j = tid>>4 (pair)
    unsigned qq = cta >> 2;                           // my chunk in every peer's buffer
    unsigned dst0 = 0, dst1 = 0, rmb_p0 = 0, rmb_p1 = 0;
    if (tid < 192) {
        unsigned P = tid & 15;
        unsigned j = (unsigned)tid >> 4;              // 0..11
        unsigned off = (qq * 100 + (cta & 3) * 24 + 2 * j) * 4;
        unsigned l0 = smem_u32(sh_h) + off;           // buf0
        unsigned l1 = l0 + 400 * 4;                   // buf1
        unsigned m0 = mbbase + (0 + qq) * 32;         // mbar[par'=0][qq]
        unsigned m1 = mbbase + (4 + qq) * 32;         // mbar[par'=1][qq]
        asm("mapa.shared::cluster.u32 %0, %1, %2;" : "=r"(dst0)   : "r"(l0), "r"(P));
        asm("mapa.shared::cluster.u32 %0, %1, %2;" : "=r"(dst1)   : "r"(l1), "r"(P));
        asm("mapa.shared::cluster.u32 %0, %1, %2;" : "=r"(rmb_p0) : "r"(m0), "r"(P));
        asm("mapa.shared::cluster.u32 %0, %1, %2;" : "=r"(rmb_p1) : "r"(m1), "r"(P));
    }

    // all buffers zeroed + mbarriers initialized cluster-wide
    asm volatile("barrier.cluster.arrive.aligned;" ::: "memory");
    asm volatile("barrier.cluster.wait.aligned;"   ::: "memory");

    const float* xwp = g_xw + (size_t)dir * SQ * G4 + (size_t)cta * 96 + (g * 24 + u);
    float c_reg = 0.0f;
    float xw_cur = __ldcg(xwp + (size_t)(dir ? SQ - 1 : 0) * G4);
    unsigned ph0 = 0, ph1 = 0;
    int lane = tid & 31;
    int gbase = (lane & 16) | q;     // lane of (this unit, gate 0, my q)
    int hidx = (int)cta * 24 + u;
    unsigned my_mb0 = mbbase + (0 + (unsigned)q) * 32;  // my chunk, parity buf 0
    unsigned my_mb1 = mbbase + (4 + (unsigned)q) * 32;  // my chunk, parity buf 1

    for (int t = 0; t < SQ; t++) {
        int par = t & 1;

        // prefetch next step's xw before the wait
        float xw_next = 0.0f;
        if (t + 1 < SQ) {
            int tn = dir ? (SQ - 2 - t) : (t + 1);
            xw_next = __ldcg(xwp + (size_t)tn * G4);
        }

        // wait for this step's chunk of the h buffer (t=0 consumes zeros)
        if (t > 0) {
            if (par) {
                mbar_wait(my_mb1, ph1); ph1 ^= 1;
                if (tid < 4) mbar_expect(my_mb1, 384);
            } else {
                mbar_wait(my_mb0, ph0); ph0 ^= 1;
                if (tid < 4) mbar_expect(my_mb0, 384);
            }
        }

        // MAC: row (g*24+u), k-chunk q
        const ulonglong2* hp2 =
            reinterpret_cast<const ulonglong2*>(sh_h + par * 400 + q * 100);
        ull a0 = 0ull, a1 = 0ull, a2 = 0ull, a3 = 0ull;
        #pragma unroll
        for (int j = 0; j < 12; j++) {
            ulonglong2 x0 = hp2[2 * j];
            ulonglong2 x1 = hp2[2 * j + 1];
            asm("fma.rn.f32x2 %0, %1, %2, %0;" : "+l"(a0) : "l"(wreg[4*j+0]), "l"(x0.x));
            asm("fma.rn.f32x2 %0, %1, %2, %0;" : "+l"(a1) : "l"(wreg[4*j+1]), "l"(x0.y));
            asm("fma.rn.f32x2 %0, %1, %2, %0;" : "+l"(a2) : "l"(wreg[4*j+2]), "l"(x1.x));
            asm("fma.rn.f32x2 %0, %1, %2, %0;" : "+l"(a3) : "l"(wreg[4*j+3]), "l"(x1.y));
        }
        asm("add.rn.f32x2 %0, %0, %1;" : "+l"(a0) : "l"(a1));
        asm("add.rn.f32x2 %0, %0, %1;" : "+l"(a2) : "l"(a3));
        asm("add.rn.f32x2 %0, %0, %1;" : "+l"(a0) : "l"(a2));
        float lo, hi;
        asm("mov.b64 {%0, %1}, %2;" : "=f"(lo), "=f"(hi) : "l"(a0));
        float s = lo + hi;
        if (q == 0) s += xw_cur;            // add xw once per row
        s += __shfl_xor_sync(0xffffffffu, s, 1);
        s += __shfl_xor_sync(0xffffffffu, s, 2);   // all 4 q-lanes: full row sum

        // gather the 4 gate sums of my unit (warp-internal)
        float gi = __shfl_sync(0xffffffffu, s, gbase + 0);
        float gf = __shfl_sync(0xffffffffu, s, gbase + 4);
        float gg = __shfl_sync(0xffffffffu, s, gbase + 8);
        float go = __shfl_sync(0xffffffffu, s, gbase + 12);

        // activation (replicated across the 16 p-lanes, deterministic)
        float cf = fast_sig(gf) * c_reg + fast_sig(gi) * fast_tanh(gg);
        c_reg = cf;
        float hv = fast_sig(go) * fast_tanh(cf);

        if (p == 0) sh_stage[par][u] = hv;
        if (p == 1) {
            int tt = dir ? (SQ - 1 - t) : t;
            g_tok[(size_t)tt * DIM + dir * HID + hidx] = hv;
        }

        __syncthreads();   // staging visible + all h reads done before any push

        if (tid < 192 && t + 1 < SQ) {
            unsigned j = (unsigned)tid >> 4;
            ull v = *reinterpret_cast<const ull*>(&sh_stage[par][2 * j]);
            unsigned dst = par ? dst0 : dst1;        // next buffer (1-par)
            unsigned rmb = par ? rmb_p0 : rmb_p1;    // its chunk mbar
            asm volatile(
                "st.async.shared::cluster.mbarrier::complete_tx::bytes.b64 [%0], %1, [%2];"
                :: "r"(dst), "l"(v), "r"(rmb) : "memory");
        }

        xw_cur = xw_next;
    }

    // keep SMEM alive until all cluster CTAs are done
    asm volatile("barrier.cluster.arrive.aligned;" ::: "memory");
    asm volatile("barrier.cluster.wait.aligned;"   ::: "memory");
}

// ---------------------------------------------------------------------------
// Event mean-pool: one CTA per event
// ---------------------------------------------------------------------------
__global__ __launch_bounds__(256) void pool_kernel(const int* __restrict__ label_event)
{
    int e = blockIdx.x;
    int start = label_event[e * 3 + 0];
    int end   = label_event[e * 3 + 1];
    float inv = 1.0f / (float)(end - start);
    for (int c = threadIdx.x; c < DIM; c += 256) {
        float s = 0.0f;
        for (int r = start; r < end; r++) s += g_tok[(size_t)r * DIM + c];
        g_emb[(size_t)e * DIM + c] = s * inv;
    }
}

// ---------------------------------------------------------------------------
// MLP layer 1: hid = relu(emb @ W1^T + b1)   [1024 x 768] x [768 x 768]
// ---------------------------------------------------------------------------
__global__ __launch_bounds__(256) void gemm_mlp1_kernel(
    const float* __restrict__ W1, const float* __restrict__ b1)
{
    __shared__ float As[32][72];
    __shared__ float Bs[32][72];

    int tid = threadIdx.x;
    int bx = blockIdx.x, by = blockIdx.y;
    int tx = tid & 15, ty = tid >> 4;

    ull acc2[4][2];
    #pragma unroll
    for (int i = 0; i < 4; i++) { acc2[i][0] = 0ull; acc2[i][1] = 0ull; }

    for (int k0 = 0; k0 < DIM; k0 += 32) {
        #pragma unroll
        for (int i = 0; i < 2; i++) {
            int id = tid + i * 256;
            int r = id >> 3, c4 = id & 7;
            float4 v = *reinterpret_cast<const float4*>(g_emb + (size_t)(by * 64 + r) * DIM + k0 + c4 * 4);
            As[c4*4+0][r] = v.x; As[c4*4+1][r] = v.y; As[c4*4+2][r] = v.z; As[c4*4+3][r] = v.w;
            float4 w = *reinterpret_cast<const float4*>(W1 + (size_t)(bx * 64 + r) * DIM + k0 + c4 * 4);
            Bs[c4*4+0][r] = w.x; Bs[c4*4+1][r] = w.y; Bs[c4*4+2][r] = w.z; Bs[c4*4+3][r] = w.w;
        }
        __syncthreads();
        #pragma unroll
        for (int k = 0; k < 32; k++) {
            float4 av = *reinterpret_cast<const float4*>(&As[k][ty * 4]);
            ull b0 = *reinterpret_cast<const ull*>(&Bs[k][tx * 4]);
            ull b1v = *reinterpret_cast<const ull*>(&Bs[k][tx * 4 + 2]);
            float a_[4] = {av.x, av.y, av.z, av.w};
            #pragma unroll
            for (int i = 0; i < 4; i++) {
                ull ad;
                asm("mov.b64 %0, {%1, %1};" : "=l"(ad) : "f"(a_[i]));
                asm("fma.rn.f32x2 %0, %1, %2, %0;" : "+l"(acc2[i][0]) : "l"(ad), "l"(b0));
                asm("fma.rn.f32x2 %0, %1, %2, %0;" : "+l"(acc2[i][1]) : "l"(ad), "l"(b1v));
            }
        }
        __syncthreads();
    }

    int col0 = bx * 64 + tx * 4;
    #pragma unroll
    for (int i = 0; i < 4; i++) {
        int row = by * 64 + ty * 4 + i;
        float2 p0 = *reinterpret_cast<float2*>(&acc2[i][0]);
        float2 p1 = *reinterpret_cast<float2*>(&acc2[i][1]);
        float* o = g_hidn + (size_t)row * DIM + col0;
        o[0] = fmaxf(p0.x + b1[col0 + 0], 0.0f);
        o[1] = fmaxf(p0.y + b1[col0 + 1], 0.0f);
        o[2] = fmaxf(p1.x + b1[col0 + 2], 0.0f);
        o[3] = fmaxf(p1.y + b1[col0 + 3], 0.0f);
    }
}

// ---------------------------------------------------------------------------
// Layer 2 + log-softmax + weighted CE per event. One warp per event.
// ---------------------------------------------------------------------------
__global__ __launch_bounds__(256) void scores_kernel(
    const float* __restrict__ W2, const float* __restrict__ b2,
    const int* __restrict__ label_event, float* scores_out)
{
    int lane = threadIdx.x & 31;
    int w = threadIdx.x >> 5;
    int e = blockIdx.x * 8 + w;
    const float* hrow = g_hidn + (size_t)e * DIM;

    float s0 = 0.0f, s1 = 0.0f;
    #pragma unroll
    for (int k = 0; k < 24; k++) {
        float v = hrow[lane + 32 * k];
        s0 += v * __ldg(&W2[lane + 32 * k]);
        s1 += v * __ldg(&W2[DIM + lane + 32 * k]);
    }
    #pragma unroll
    for (int m = 16; m >= 1; m >>= 1) {
        s0 += __shfl_xor_sync(0xffffffffu, s0, m);
        s1 += __shfl_xor_sync(0xffffffffu, s1, m);
    }
    if (lane == 0) {
        s0 += b2[0]; s1 += b2[1];
        float* sp = scores_out ? scores_out : g_scores_scratch;
        sp[2 * e + 0] = s0;
        sp[2 * e + 1] = s1;
        float mx = fmaxf(s0, s1);
        float lse = mx + logf(expf(s0 - mx) + expf(s1 - mx));
        int lab = label_event[e * 3 + 2];
        float sl = lab ? s1 : s0;
        float ce = lse - sl;
        float wgt = (lab == 0) ? 1.0f : (float)lab * 1.0f;
        g_evloss[e] = ce * wgt;
    }
}

__global__ __launch_bounds__(1024) void loss_reduce_kernel(float* loss_out)
{
    __shared__ float red[1024];
    int tid = threadIdx.x;
    red[tid] = g_evloss[tid];
    __syncthreads();
    for (int s = 512; s >= 1; s >>= 1) {
        if (tid < s) red[tid] += red[tid + s];
        __syncthreads();
    }
    if (tid == 0) {
        float* lp = loss_out ? loss_out : g_loss_scratch;
        lp[0] = red[0];
    }
}

// ---------------------------------------------------------------------------
extern "C" void kernel_launch(void* const* d_in, const int* in_sizes, int n_in,
                              void* d_out, int out_size) {
    const float* X     = (const float*)d_in[0];
    const int*   lev   = (const int*)  d_in[1];
    const float* Wih_f = (const float*)d_in[2];
    const float* Whh_f = (const float*)d_in[3];
    const float* bih_f = (const float*)d_in[4];
    const float* bhh_f = (const float*)d_in[5];
    const float* Wih_b = (const float*)d_in[6];
    const float* Whh_b = (const float*)d_in[7];
    const float* bih_b = (const float*)d_in[8];
    const float* bhh_b = (const float*)d_in[9];
    const float* W1    = (const float*)d_in[10];
    const float* b1    = (const float*)d_in[11];
    const float* W2    = (const float*)d_in[12];
    const float* b2    = (const float*)d_in[13];

    float* out = (float*)d_out;
    float* loss_ptr   = nullptr;
    float* scores_ptr = nullptr;
    if (out_size >= 2049)      { loss_ptr = out; scores_ptr = out + 1; }
    else if (out_size >= 2048) { scores_ptr = out; }
    else                       { loss_ptr = out; }

    gemm_xw_kernel<<<dim3(48, 64), 256>>>(X, Wih_f, Wih_b, bih_f, bhh_f, bih_b, bhh_b);

    // LSTM: 2 clusters of 16 CTAs (non-portable cluster size)
    cudaFuncSetAttribute((const void*)lstm_kernel,
                         cudaFuncAttributeNonPortableClusterSizeAllowed, 1);
    cudaLaunchConfig_t cfg = {};
    cfg.gridDim  = dim3(32, 1, 1);
    cfg.blockDim = dim3(384, 1, 1);
    cfg.dynamicSmemBytes = 0;
    cudaLaunchAttribute attrs[1];
    attrs[0].id = cudaLaunchAttributeClusterDimension;
    attrs[0].val.clusterDim.x = 16;
    attrs[0].val.clusterDim.y = 1;
    attrs[0].val.clusterDim.z = 1;
    cfg.attrs = attrs;
    cfg.numAttrs = 1;
    cudaLaunchKernelEx(&cfg, lstm_kernel, Whh_f, Whh_b);

    pool_kernel<<<NEV, 256>>>(lev);
    gemm_mlp1_kernel<<<dim3(12, 16), 256>>>(W1, b1);
    scores_kernel<<<NEV / 8, 256>>>(W2, b2, lev, scores_ptr);
    loss_reduce_kernel<<<1, 1024>>>(loss_ptr);
}

// round 14
// speedup vs baseline: 1.2528x; 1.2198x over previous
#include <cuda_runtime.h>
#include <cuda_bf16.h>
#include <cstdint>

typedef unsigned long long ull;

#define SQ   4096
#define DIM  768
#define HID  384
#define G4   1536
#define NEV  1024

// ---------------- static scratch (no runtime allocation) ----------------
__device__ float g_xw[2u * SQ * G4];    // permuted gate preactivations, both dirs
__device__ float g_tok[(size_t)SQ * DIM];
__device__ float g_emb[NEV * DIM];
__device__ float g_hidn[NEV * DIM];
__device__ float g_evloss[NEV];
__device__ float g_scores_scratch[2 * NEV];
__device__ float g_loss_scratch[1];

// accuracy-safe fast activations (validated at rel_err 4e-6)
__device__ __forceinline__ float fast_sig(float x) {
    return __fdividef(1.0f, 1.0f + __expf(-x));
}
__device__ __forceinline__ float fast_tanh(float x) {
    return 1.0f - __fdividef(2.0f, __expf(2.0f * x) + 1.0f);
}

__device__ __forceinline__ unsigned smem_u32(const void* p) {
    unsigned a;
    asm("{ .reg .u64 t; cvta.to.shared.u64 t, %1; cvt.u32.u64 %0, t; }" : "=r"(a) : "l"(p));
    return a;
}

__device__ __forceinline__ void mbar_wait(unsigned mbar, unsigned parity) {
    unsigned done;
    asm volatile("{\n\t.reg .pred p;\n\t"
        "mbarrier.try_wait.parity.acquire.cluster.shared::cta.b64 p, [%1], %2;\n\t"
        "selp.b32 %0, 1, 0, p;\n\t}"
        : "=r"(done) : "r"(mbar), "r"(parity) : "memory");
    while (!done) {
        asm volatile("{\n\t.reg .pred p;\n\t"
            "mbarrier.try_wait.parity.acquire.cluster.shared::cta.b64 p, [%1], %2, 0x989680;\n\t"
            "selp.b32 %0, 1, 0, p;\n\t}"
            : "=r"(done) : "r"(mbar), "r"(parity) : "memory");
    }
}

__device__ __forceinline__ void mbar_expect(unsigned mbar, unsigned bytes) {
    asm volatile("mbarrier.arrive.expect_tx.shared.b64 _, [%0], %1;"
                 :: "r"(mbar), "r"(bytes) : "memory");
}

// dummy launches to shift ncu's captured launch (#4) onto lstm_kernel
__global__ void dummy_kernel() {}

// ---------------------------------------------------------------------------
// GEMM A: xw[d][t][jj] = X[t] . W_d[orig(jj)] + (bih+bhh)[orig]
// column permutation: jj = cta*96 + gate*24 + u  <->  orig = gate*384 + cta*24 + u
// ---------------------------------------------------------------------------
__global__ __launch_bounds__(256) void gemm_xw_kernel(
    const float* __restrict__ X,
    const float* __restrict__ Wf, const float* __restrict__ Wb,
    const float* __restrict__ bihf, const float* __restrict__ bhhf,
    const float* __restrict__ bihb, const float* __restrict__ bhhb)
{
    __shared__ float As[32][72];
    __shared__ float Bs[32][72];
    __shared__ const float* wptr[64];
    __shared__ float biasv[64];

    int tid = threadIdx.x;
    int bx = blockIdx.x, by = blockIdx.y;

    if (tid < 64) {
        int jp = bx * 64 + tid;          // 0..3071
        int d  = jp / G4;
        int jj = jp - d * G4;
        int cc = jj / 96, ll = jj % 96;
        int orig = (ll / 24) * HID + cc * 24 + (ll % 24);
        wptr[tid]  = (d ? Wb : Wf) + (size_t)orig * DIM;
        biasv[tid] = d ? (bihb[orig] + bhhb[orig]) : (bihf[orig] + bhhf[orig]);
    }
    __syncthreads();

    int tx = tid & 15, ty = tid >> 4;
    ull acc2[4][2];
    #pragma unroll
    for (int i = 0; i < 4; i++) { acc2[i][0] = 0ull; acc2[i][1] = 0ull; }

    for (int k0 = 0; k0 < DIM; k0 += 32) {
        #pragma unroll
        for (int i = 0; i < 2; i++) {
            int id = tid + i * 256;
            int r = id >> 3, c4 = id & 7;
            float4 v = *reinterpret_cast<const float4*>(X + (size_t)(by * 64 + r) * DIM + k0 + c4 * 4);
            As[c4*4+0][r] = v.x; As[c4*4+1][r] = v.y; As[c4*4+2][r] = v.z; As[c4*4+3][r] = v.w;
            float4 w = *reinterpret_cast<const float4*>(wptr[r] + k0 + c4 * 4);
            Bs[c4*4+0][r] = w.x; Bs[c4*4+1][r] = w.y; Bs[c4*4+2][r] = w.z; Bs[c4*4+3][r] = w.w;
        }
        __syncthreads();
        #pragma unroll
        for (int k = 0; k < 32; k++) {
            float4 av = *reinterpret_cast<const float4*>(&As[k][ty * 4]);
            ull b0 = *reinterpret_cast<const ull*>(&Bs[k][tx * 4]);
            ull b1 = *reinterpret_cast<const ull*>(&Bs[k][tx * 4 + 2]);
            float a_[4] = {av.x, av.y, av.z, av.w};
            #pragma unroll
            for (int i = 0; i < 4; i++) {
                ull ad;
                asm("mov.b64 %0, {%1, %1};" : "=l"(ad) : "f"(a_[i]));
                asm("fma.rn.f32x2 %0, %1, %2, %0;" : "+l"(acc2[i][0]) : "l"(ad), "l"(b0));
                asm("fma.rn.f32x2 %0, %1, %2, %0;" : "+l"(acc2[i][1]) : "l"(ad), "l"(b1));
            }
        }
        __syncthreads();
    }

    int d = (bx * 64) / G4;
    size_t outbase = (size_t)d * SQ * G4;
    int col0 = bx * 64 - d * G4 + tx * 4;
    #pragma unroll
    for (int i = 0; i < 4; i++) {
        int t = by * 64 + ty * 4 + i;
        float2 p0 = *reinterpret_cast<float2*>(&acc2[i][0]);
        float2 p1 = *reinterpret_cast<float2*>(&acc2[i][1]);
        float* o = g_xw + outbase + (size_t)t * G4 + col0;
        o[0] = p0.x + biasv[tx*4+0];
        o[1] = p0.y + biasv[tx*4+1];
        o[2] = p1.x + biasv[tx*4+2];
        o[3] = p1.y + biasv[tx*4+3];
    }
}

// ---------------------------------------------------------------------------
// LSTM: one 16-CTA cluster per direction. Weights register-resident.
// R5 push-immediately structure (measured 4970us; R9/R13 variants with
// post-activation staging/sync regressed — push issue time is the critical
// path) with ONE change: 4 per-chunk mbarriers per parity.
//   MAC roles: rr = tid>>2 (row), q = tid&3 (96-float k-chunk).
//   Activation roles: u = tid%24 (unit), peer = tid/24 (dest CTA);
//     c replicated 16x; each thread pushes hv for (u -> peer) directly
//     via st.async.b32 right after activation, completing on the
//     destination's chunk mbar (chunk cta/4; all 24 of a CTA's units lie
//     in one chunk).
//   Each thread waits ONLY chunk q's mbar (96 B x 4 source CTAs = 384 B);
//   threads 0..3 (rr=0, q=tid) re-arm chunk q after their wait.
// Reuse safety: reads < __syncthreads < pushes per CTA; peer's chunk-waits
// union to all 16 CTAs at its __syncthreads -> transitive chain holds.
// ---------------------------------------------------------------------------
__global__ __launch_bounds__(384, 1) void lstm_kernel(
    const float* __restrict__ Whh_f, const float* __restrict__ Whh_b)
{
    __shared__ __align__(16) float sh_h[2 * 400];    // [buf][chunk q at q*100]
    __shared__ float sh_gate[2][96];                 // double-buffered by parity
    __shared__ __align__(8) ull sh_mbar[32];         // mbar (buf*4+chunk) at idx*4 (32B apart)

    int tid = threadIdx.x;
    int dir = blockIdx.x >> 4;
    unsigned cta;
    asm("mov.u32 %0, %%cluster_ctarank;" : "=r"(cta));

    int rr = tid >> 2, q = tid & 3;
    int u = tid % 24, peer = tid / 24;
    int gate = rr / 24, uu = rr % 24;
    int orig = gate * HID + (int)cta * 24 + uu;

    const float* Whh = dir ? Whh_b : Whh_f;
    const ull* wrow = reinterpret_cast<const ull*>(Whh + (size_t)orig * HID + q * 96);
    ull wreg[48];
    #pragma unroll
    for (int j = 0; j < 48; j++) wreg[j] = wrow[j];

    // zero both h buffers
    for (int i = tid; i < 2 * 400; i += 384) sh_h[i] = 0.0f;

    unsigned mbbase = smem_u32(&sh_mbar[0]);
    if (tid == 0) {
        #pragma unroll
        for (int i = 0; i < 8; i++) {
            unsigned mb = mbbase + i * 32;
            asm volatile("mbarrier.init.shared.b64 [%0], 1;" :: "r"(mb) : "memory");
            mbar_expect(mb, 384);
        }
        asm volatile("fence.mbarrier_init.release.cluster;" ::: "memory");
    }
    __syncthreads();

    // push setup: thread (u, peer) pushes hidx = cta*24+u into peer's buffers
    int hidx = (int)cta * 24 + u;
    unsigned qq = cta >> 2;                 // chunk my CTA's units land in
    int mm = hidx % 96;
    unsigned loc0 = smem_u32(sh_h) + (qq * 100 + (unsigned)mm) * 4;   // buf0
    unsigned loc1 = loc0 + 400 * 4;                                    // buf1
    unsigned m0 = mbbase + (0 * 4 + qq) * 32;   // chunk mbar, buf0
    unsigned m1 = mbbase + (1 * 4 + qq) * 32;   // chunk mbar, buf1
    unsigned rem0, rem1, rmbB0, rmbB1;
    asm("mapa.shared::cluster.u32 %0, %1, %2;" : "=r"(rem0)  : "r"(loc0), "r"(peer));
    asm("mapa.shared::cluster.u32 %0, %1, %2;" : "=r"(rem1)  : "r"(loc1), "r"(peer));
    asm("mapa.shared::cluster.u32 %0, %1, %2;" : "=r"(rmbB0) : "r"(m0),   "r"(peer));
    asm("mapa.shared::cluster.u32 %0, %1, %2;" : "=r"(rmbB1) : "r"(m1),   "r"(peer));

    // all buffers zeroed + mbarriers initialized cluster-wide
    asm volatile("barrier.cluster.arrive.aligned;" ::: "memory");
    asm volatile("barrier.cluster.wait.aligned;"   ::: "memory");

    const float* xwp = g_xw + (size_t)dir * SQ * G4 + (size_t)cta * 96 + rr;
    float c_reg = 0.0f;
    float xw_cur = (q == 0) ? __ldcg(xwp + (size_t)(dir ? SQ - 1 : 0) * G4) : 0.0f;
    unsigned ph0 = 0, ph1 = 0;
    unsigned my_mb0 = mbbase + (0 * 4 + (unsigned)q) * 32;   // my wait chunk, buf0
    unsigned my_mb1 = mbbase + (1 * 4 + (unsigned)q) * 32;   // my wait chunk, buf1

    for (int t = 0; t < SQ; t++) {
        int par = t & 1;

        // prefetch next step's xw before the wait
        float xw_next = 0.0f;
        if (q == 0 && t + 1 < SQ) {
            int tn = dir ? (SQ - 2 - t) : (t + 1);
            xw_next = __ldcg(xwp + (size_t)tn * G4);
        }

        // wait for this step's chunk of the h buffer (t=0 consumes zeros)
        if (t > 0) {
            if (par) {
                mbar_wait(my_mb1, ph1); ph1 ^= 1;
                if (tid < 4) mbar_expect(my_mb1, 384);
            } else {
                mbar_wait(my_mb0, ph0); ph0 ^= 1;
                if (tid < 4) mbar_expect(my_mb0, 384);
            }
        }

        // MAC: row rr, k-chunk q
        const ulonglong2* hp2 =
            reinterpret_cast<const ulonglong2*>(sh_h + par * 400 + q * 100);
        ull a0 = 0ull, a1 = 0ull, a2 = 0ull, a3 = 0ull;
        #pragma unroll
        for (int j = 0; j < 12; j++) {
            ulonglong2 x0 = hp2[2 * j];
            ulonglong2 x1 = hp2[2 * j + 1];
            asm("fma.rn.f32x2 %0, %1, %2, %0;" : "+l"(a0) : "l"(wreg[4*j+0]), "l"(x0.x));
            asm("fma.rn.f32x2 %0, %1, %2, %0;" : "+l"(a1) : "l"(wreg[4*j+1]), "l"(x0.y));
            asm("fma.rn.f32x2 %0, %1, %2, %0;" : "+l"(a2) : "l"(wreg[4*j+2]), "l"(x1.x));
            asm("fma.rn.f32x2 %0, %1, %2, %0;" : "+l"(a3) : "l"(wreg[4*j+3]), "l"(x1.y));
        }
        asm("add.rn.f32x2 %0, %0, %1;" : "+l"(a0) : "l"(a1));
        asm("add.rn.f32x2 %0, %0, %1;" : "+l"(a2) : "l"(a3));
        asm("add.rn.f32x2 %0, %0, %1;" : "+l"(a0) : "l"(a2));
        float lo, hi;
        asm("mov.b64 {%0, %1}, %2;" : "=f"(lo), "=f"(hi) : "l"(a0));
        float s = lo + hi;
        s += __shfl_xor_sync(0xffffffffu, s, 1);
        s += __shfl_xor_sync(0xffffffffu, s, 2);
        if (q == 0) sh_gate[par][rr] = s + xw_cur;
        __syncthreads();   // orders ALL h/gate reads before any push below

        // activation (replicated across the 16 peer-groups, deterministic)
        float gi = sh_gate[par][u],      gf = sh_gate[par][24 + u];
        float gg = sh_gate[par][48 + u], go = sh_gate[par][72 + u];
        float cf = fast_sig(gf) * c_reg + fast_sig(gi) * fast_tanh(gg);
        c_reg = cf;
        float hv = fast_sig(go) * fast_tanh(cf);

        // push my unit's h into peer's buf[1-par] IMMEDIATELY (critical path)
        if (t + 1 < SQ) {
            unsigned rem = par ? rem0 : rem1;      // next buffer
            unsigned rmb = par ? rmbB0 : rmbB1;    // its chunk mbar
            asm volatile("st.async.shared::cluster.mbarrier::complete_tx::bytes.b32 [%0], %1, [%2];"
                         :: "r"(rem), "r"(__float_as_uint(hv)), "r"(rmb) : "memory");
        }

        if (peer == 0) {
            int tt = dir ? (SQ - 1 - t) : t;
            g_tok[(size_t)tt * DIM + dir * HID + hidx] = hv;
        }

        xw_cur = xw_next;
    }

    // keep SMEM alive until all cluster CTAs are done
    asm volatile("barrier.cluster.arrive.aligned;" ::: "memory");
    asm volatile("barrier.cluster.wait.aligned;"   ::: "memory");
}

// ---------------------------------------------------------------------------
// Event mean-pool: one CTA per event
// ---------------------------------------------------------------------------
__global__ __launch_bounds__(256) void pool_kernel(const int* __restrict__ label_event)
{
    int e = blockIdx.x;
    int start = label_event[e * 3 + 0];
    int end   = label_event[e * 3 + 1];
    float inv = 1.0f / (float)(end - start);
    for (int c = threadIdx.x; c < DIM; c += 256) {
        float s = 0.0f;
        for (int r = start; r < end; r++) s += g_tok[(size_t)r * DIM + c];
        g_emb[(size_t)e * DIM + c] = s * inv;
    }
}

// ---------------------------------------------------------------------------
// MLP layer 1: hid = relu(emb @ W1^T + b1)   [1024 x 768] x [768 x 768]
// ---------------------------------------------------------------------------
__global__ __launch_bounds__(256) void gemm_mlp1_kernel(
    const float* __restrict__ W1, const float* __restrict__ b1)
{
    __shared__ float As[32][72];
    __shared__ float Bs[32][72];

    int tid = threadIdx.x;
    int bx = blockIdx.x, by = blockIdx.y;
    int tx = tid & 15, ty = tid >> 4;

    ull acc2[4][2];
    #pragma unroll
    for (int i = 0; i < 4; i++) { acc2[i][0] = 0ull; acc2[i][1] = 0ull; }

    for (int k0 = 0; k0 < DIM; k0 += 32) {
        #pragma unroll
        for (int i = 0; i < 2; i++) {
            int id = tid + i * 256;
            int r = id >> 3, c4 = id & 7;
            float4 v = *reinterpret_cast<const float4*>(g_emb + (size_t)(by * 64 + r) * DIM + k0 + c4 * 4);
            As[c4*4+0][r] = v.x; As[c4*4+1][r] = v.y; As[c4*4+2][r] = v.z; As[c4*4+3][r] = v.w;
            float4 w = *reinterpret_cast<const float4*>(W1 + (size_t)(bx * 64 + r) * DIM + k0 + c4 * 4);
            Bs[c4*4+0][r] = w.x; Bs[c4*4+1][r] = w.y; Bs[c4*4+2][r] = w.z; Bs[c4*4+3][r] = w.w;
        }
        __syncthreads();
        #pragma unroll
        for (int k = 0; k < 32; k++) {
            float4 av = *reinterpret_cast<const float4*>(&As[k][ty * 4]);
            ull b0 = *reinterpret_cast<const ull*>(&Bs[k][tx * 4]);
            ull b1v = *reinterpret_cast<const ull*>(&Bs[k][tx * 4 + 2]);
            float a_[4] = {av.x, av.y, av.z, av.w};
            #pragma unroll
            for (int i = 0; i < 4; i++) {
                ull ad;
                asm("mov.b64 %0, {%1, %1};" : "=l"(ad) : "f"(a_[i]));
                asm("fma.rn.f32x2 %0, %1, %2, %0;" : "+l"(acc2[i][0]) : "l"(ad), "l"(b0));
                asm("fma.rn.f32x2 %0, %1, %2, %0;" : "+l"(acc2[i][1]) : "l"(ad), "l"(b1v));
            }
        }
        __syncthreads();
    }

    int col0 = bx * 64 + tx * 4;
    #pragma unroll
    for (int i = 0; i < 4; i++) {
        int row = by * 64 + ty * 4 + i;
        float2 p0 = *reinterpret_cast<float2*>(&acc2[i][0]);
        float2 p1 = *reinterpret_cast<float2*>(&acc2[i][1]);
        float* o = g_hidn + (size_t)row * DIM + col0;
        o[0] = fmaxf(p0.x + b1[col0 + 0], 0.0f);
        o[1] = fmaxf(p0.y + b1[col0 + 1], 0.0f);
        o[2] = fmaxf(p1.x + b1[col0 + 2], 0.0f);
        o[3] = fmaxf(p1.y + b1[col0 + 3], 0.0f);
    }
}

// ---------------------------------------------------------------------------
// Layer 2 + log-softmax + weighted CE per event. One warp per event.
// ---------------------------------------------------------------------------
__global__ __launch_bounds__(256) void scores_kernel(
    const float* __restrict__ W2, const float* __restrict__ b2,
    const int* __restrict__ label_event, float* scores_out)
{
    int lane = threadIdx.x & 31;
    int w = threadIdx.x >> 5;
    int e = blockIdx.x * 8 + w;
    const float* hrow = g_hidn + (size_t)e * DIM;

    float s0 = 0.0f, s1 = 0.0f;
    #pragma unroll
    for (int k = 0; k < 24; k++) {
        float v = hrow[lane + 32 * k];
        s0 += v * __ldg(&W2[lane + 32 * k]);
        s1 += v * __ldg(&W2[DIM + lane + 32 * k]);
    }
    #pragma unroll
    for (int m = 16; m >= 1; m >>= 1) {
        s0 += __shfl_xor_sync(0xffffffffu, s0, m);
        s1 += __shfl_xor_sync(0xffffffffu, s1, m);
    }
    if (lane == 0) {
        s0 += b2[0]; s1 += b2[1];
        float* sp = scores_out ? scores_out : g_scores_scratch;
        sp[2 * e + 0] = s0;
        sp[2 * e + 1] = s1;
        float mx = fmaxf(s0, s1);
        float lse = mx + logf(expf(s0 - mx) + expf(s1 - mx));
        int lab = label_event[e * 3 + 2];
        float sl = lab ? s1 : s0;
        float ce = lse - sl;
        float wgt = (lab == 0) ? 1.0f : (float)lab * 1.0f;
        g_evloss[e] = ce * wgt;
    }
}

__global__ __launch_bounds__(1024) void loss_reduce_kernel(float* loss_out)
{
    __shared__ float red[1024];
    int tid = threadIdx.x;
    red[tid] = g_evloss[tid];
    __syncthreads();
    for (int s = 512; s >= 1; s >>= 1) {
        if (tid < s) red[tid] += red[tid + s];
        __syncthreads();
    }
    if (tid == 0) {
        float* lp = loss_out ? loss_out : g_loss_scratch;
        lp[0] = red[0];
    }
}

// ---------------------------------------------------------------------------
extern "C" void kernel_launch(void* const* d_in, const int* in_sizes, int n_in,
                              void* d_out, int out_size) {
    const float* X     = (const float*)d_in[0];
    const int*   lev   = (const int*)  d_in[1];
    const float* Wih_f = (const float*)d_in[2];
    const float* Whh_f = (const float*)d_in[3];
    const float* bih_f = (const float*)d_in[4];
    const float* bhh_f = (const float*)d_in[5];
    const float* Wih_b = (const float*)d_in[6];
    const float* Whh_b = (const float*)d_in[7];
    const float* bih_b = (const float*)d_in[8];
    const float* bhh_b = (const float*)d_in[9];
    const float* W1    = (const float*)d_in[10];
    const float* b1    = (const float*)d_in[11];
    const float* W2    = (const float*)d_in[12];
    const float* b2    = (const float*)d_in[13];

    float* out = (float*)d_out;
    float* loss_ptr   = nullptr;
    float* scores_ptr = nullptr;
    if (out_size >= 2049)      { loss_ptr = out; scores_ptr = out + 1; }
    else if (out_size >= 2048) { scores_ptr = out; }
    else                       { loss_ptr = out; }

    gemm_xw_kernel<<<dim3(48, 64), 256>>>(X, Wih_f, Wih_b, bih_f, bhh_f, bih_b, bhh_b);

    // two dummy launches so ncu's captured launch (#4) is lstm_kernel
    dummy_kernel<<<1, 32>>>();
    dummy_kernel<<<1, 32>>>();

    // LSTM: 2 clusters of 16 CTAs (non-portable cluster size)
    cudaFuncSetAttribute((const void*)lstm_kernel,
                         cudaFuncAttributeNonPortableClusterSizeAllowed, 1);
    cudaLaunchConfig_t cfg = {};
    cfg.gridDim  = dim3(32, 1, 1);
    cfg.blockDim = dim3(384, 1, 1);
    cfg.dynamicSmemBytes = 0;
    cudaLaunchAttribute attrs[1];
    attrs[0].id = cudaLaunchAttributeClusterDimension;
    attrs[0].val.clusterDim.x = 16;
    attrs[0].val.clusterDim.y = 1;
    attrs[0].val.clusterDim.z = 1;
    cfg.attrs = attrs;
    cfg.numAttrs = 1;
    cudaLaunchKernelEx(&cfg, lstm_kernel, Whh_f, Whh_b);

    pool_kernel<<<NEV, 256>>>(lev);
    gemm_mlp1_kernel<<<dim3(12, 16), 256>>>(W1, b1);
    scores_kernel<<<NEV / 8, 256>>>(W2, b2, lev, scores_ptr);
    loss_reduce_kernel<<<1, 1024>>>(loss_ptr);
}

// round 15
// speedup vs baseline: 1.5654x; 1.2495x over previous
#include <cuda_runtime.h>
#include <cuda_bf16.h>
#include <cstdint>

typedef unsigned long long ull;

#define SQ   4096
#define DIM  768
#define HID  384
#define G4   1536
#define NEV  1024

// ---------------- static scratch (no runtime allocation) ----------------
__device__ float g_xw[2u * SQ * G4];    // permuted gate preactivations, both dirs
__device__ float g_tok[(size_t)SQ * DIM];
__device__ float g_emb[NEV * DIM];
__device__ float g_hidn[NEV * DIM];
__device__ float g_evloss[NEV];
__device__ float g_scores_scratch[2 * NEV];
__device__ float g_loss_scratch[1];
__device__ unsigned g_prog[128];        // [dir][time-tile] completed bx-tile count (24 = ready)

__global__ void init_kernel() {
    if (threadIdx.x < 128) g_prog[threadIdx.x] = 0u;
}

// dummy launches so ncu's captured launch (#4) is the fused kernel
__global__ void dummy_kernel() {}

// MUFU-based activations. tanh.approx exonerated by R7/R8 A-B (error was the
// staging-parity bug, identical with/without approx). ~60-80 cyc off the
// serial activation chain per step.
__device__ __forceinline__ float tanh_mufu(float x) {
    float y;
    asm("tanh.approx.f32 %0, %1;" : "=f"(y) : "f"(x));
    return y;
}
__device__ __forceinline__ float sig_mufu(float x) {
    return fmaf(0.5f, tanh_mufu(0.5f * x), 0.5f);
}

__device__ __forceinline__ unsigned smem_u32(const void* p) {
    unsigned a;
    asm("{ .reg .u64 t; cvta.to.shared.u64 t, %1; cvt.u32.u64 %0, t; }" : "=r"(a) : "l"(p));
    return a;
}

__device__ __forceinline__ void mbar_wait(unsigned mbar, unsigned parity) {
    unsigned done;
    asm volatile("{\n\t.reg .pred p;\n\t"
        "mbarrier.try_wait.parity.acquire.cluster.shared::cta.b64 p, [%1], %2;\n\t"
        "selp.b32 %0, 1, 0, p;\n\t}"
        : "=r"(done) : "r"(mbar), "r"(parity) : "memory");
    while (!done) {
        asm volatile("{\n\t.reg .pred p;\n\t"
            "mbarrier.try_wait.parity.acquire.cluster.shared::cta.b64 p, [%1], %2, 0x989680;\n\t"
            "selp.b32 %0, 1, 0, p;\n\t}"
            : "=r"(done) : "r"(mbar), "r"(parity) : "memory");
    }
}

__device__ __forceinline__ void mbar_expect(unsigned mbar, unsigned bytes) {
    asm volatile("mbarrier.arrive.expect_tx.shared.b64 _, [%0], %1;"
                 :: "r"(mbar), "r"(bytes) : "memory");
}

__device__ __forceinline__ void prog_poll(const unsigned* pp) {
    unsigned v;
    do {
        asm volatile("ld.acquire.gpu.global.u32 %0, [%1];" : "=r"(v) : "l"(pp) : "memory");
    } while (v < 24u);
}

// ---------------------------------------------------------------------------
// GEMM tile body (runs in blocks 32.. of the fused kernel; 256 active threads,
// all 384 participate in __syncthreads). Tile g: r = g/48 (epoch), j = g%48;
// j<24 -> dir0 by=r bx24=j ; j>=24 -> dir1 by=63-r bx24=j-24. So epoch r
// produces forward row r AND backward row 63-r — exactly the LSTM's demand
// order. Signals g_prog[d*64+by] with release semantics when done.
// ---------------------------------------------------------------------------
__device__ void gemm_tile_body(
    int g, int tid,
    const float* __restrict__ X,
    const float* __restrict__ Wf, const float* __restrict__ Wb,
    const float* __restrict__ bihf, const float* __restrict__ bhhf,
    const float* __restrict__ bihb, const float* __restrict__ bhhb)
{
    __shared__ float As[32][72];
    __shared__ float Bs[32][72];
    __shared__ const float* wptr[64];
    __shared__ float biasv[64];

    int r = g / 48, j = g % 48;
    int d = (j < 24) ? 0 : 1;
    int by = d ? (63 - r) : r;
    int bx = d ? (24 + (j - 24)) : j;      // global bx 0..47 (matches jp layout)

    if (tid < 64) {
        int jp = bx * 64 + tid;            // 0..3071
        int jj = jp - d * G4;
        int cc = jj / 96, ll = jj % 96;
        int orig = (ll / 24) * HID + cc * 24 + (ll % 24);
        wptr[tid]  = (d ? Wb : Wf) + (size_t)orig * DIM;
        biasv[tid] = d ? (bihb[orig] + bhhb[orig]) : (bihf[orig] + bhhf[orig]);
    }
    __syncthreads();

    int tx = tid & 15, ty = (tid >> 4) & 15;   // ty valid for tid<256
    bool active = (tid < 256);
    ull acc2[4][2];
    #pragma unroll
    for (int i = 0; i < 4; i++) { acc2[i][0] = 0ull; acc2[i][1] = 0ull; }

    for (int k0 = 0; k0 < DIM; k0 += 32) {
        if (active) {
            #pragma unroll
            for (int i = 0; i < 2; i++) {
                int id = tid + i * 256;
                int rr = id >> 3, c4 = id & 7;
                float4 v = *reinterpret_cast<const float4*>(X + (size_t)(by * 64 + rr) * DIM + k0 + c4 * 4);
                As[c4*4+0][rr] = v.x; As[c4*4+1][rr] = v.y; As[c4*4+2][rr] = v.z; As[c4*4+3][rr] = v.w;
                float4 w = *reinterpret_cast<const float4*>(wptr[rr] + k0 + c4 * 4);
                Bs[c4*4+0][rr] = w.x; Bs[c4*4+1][rr] = w.y; Bs[c4*4+2][rr] = w.z; Bs[c4*4+3][rr] = w.w;
            }
        }
        __syncthreads();
        if (active) {
            #pragma unroll
            for (int k = 0; k < 32; k++) {
                float4 av = *reinterpret_cast<const float4*>(&As[k][ty * 4]);
                ull b0 = *reinterpret_cast<const ull*>(&Bs[k][tx * 4]);
                ull b1 = *reinterpret_cast<const ull*>(&Bs[k][tx * 4 + 2]);
                float a_[4] = {av.x, av.y, av.z, av.w};
                #pragma unroll
                for (int i = 0; i < 4; i++) {
                    ull ad;
                    asm("mov.b64 %0, {%1, %1};" : "=l"(ad) : "f"(a_[i]));
                    asm("fma.rn.f32x2 %0, %1, %2, %0;" : "+l"(acc2[i][0]) : "l"(ad), "l"(b0));
                    asm("fma.rn.f32x2 %0, %1, %2, %0;" : "+l"(acc2[i][1]) : "l"(ad), "l"(b1));
                }
            }
        }
        __syncthreads();
    }

    if (active) {
        size_t outbase = (size_t)d * SQ * G4;
        int col0 = bx * 64 - d * G4 + tx * 4;
        #pragma unroll
        for (int i = 0; i < 4; i++) {
            int t = by * 64 + ty * 4 + i;
            float2 p0 = *reinterpret_cast<float2*>(&acc2[i][0]);
            float2 p1 = *reinterpret_cast<float2*>(&acc2[i][1]);
            float* o = g_xw + outbase + (size_t)t * G4 + col0;
            o[0] = p0.x + biasv[tx*4+0];
            o[1] = p0.y + biasv[tx*4+1];
            o[2] = p1.x + biasv[tx*4+2];
            o[3] = p1.y + biasv[tx*4+3];
        }
    }
    __threadfence();
    __syncthreads();
    if (tid == 0) {
        asm volatile("red.release.gpu.global.add.u32 [%0], %1;"
                     :: "l"(g_prog + d * 64 + by), "r"(1u) : "memory");
    }
}

// ---------------------------------------------------------------------------
// LSTM body (blocks 0..31; 2 clusters of 16). Exact R5 protocol (best
// measured: single mbar/parity, STS gate exchange, push-immediately) with
// MUFU activations and xw-readiness polling at 64-step row boundaries.
//   MAC roles: rr = tid>>2 (row), q = tid&3 (96-float k-chunk).
//   Activation roles: u = tid%24 (unit), peer = tid/24; c replicated 16x;
//   each thread pushes hv(u) to peer's next buffer via st.async.b32 right
//   after activation (critical path = push issue time).
// ---------------------------------------------------------------------------
__device__ void lstm_body(
    const float* __restrict__ Whh_f, const float* __restrict__ Whh_b)
{
    __shared__ __align__(16) float sh_h[2 * 400];    // [buf][chunk q at q*100]
    __shared__ float sh_gate[2][96];                 // double-buffered by parity
    __shared__ __align__(8) ull sh_mbar[2];

    int tid = threadIdx.x;
    int dir = blockIdx.x >> 4;
    unsigned cta;
    asm("mov.u32 %0, %%cluster_ctarank;" : "=r"(cta));

    int rr = tid >> 2, q = tid & 3;
    int u = tid % 24, peer = tid / 24;
    int gate = rr / 24, uu = rr % 24;
    int orig = gate * HID + (int)cta * 24 + uu;

    const float* Whh = dir ? Whh_b : Whh_f;
    const ull* wrow = reinterpret_cast<const ull*>(Whh + (size_t)orig * HID + q * 96);
    ull wreg[48];
    #pragma unroll
    for (int j = 0; j < 48; j++) wreg[j] = wrow[j];

    for (int i = tid; i < 2 * 400; i += 384) sh_h[i] = 0.0f;

    unsigned mb0 = smem_u32(&sh_mbar[0]);
    unsigned mb1 = mb0 + 8;
    if (tid == 0) {
        asm volatile("mbarrier.init.shared.b64 [%0], 1;" :: "r"(mb0) : "memory");
        asm volatile("mbarrier.init.shared.b64 [%0], 1;" :: "r"(mb1) : "memory");
        mbar_expect(mb0, 1536);
        mbar_expect(mb1, 1536);
        asm volatile("fence.mbarrier_init.release.cluster;" ::: "memory");
    }
    __syncthreads();

    // push setup: thread (u, peer) pushes hidx = cta*24+u into peer's buffers
    int hidx = (int)cta * 24 + u;
    unsigned qq = cta >> 2;
    int mm = hidx % 96;
    unsigned loc0 = smem_u32(sh_h) + (qq * 100 + (unsigned)mm) * 4;   // buf0
    unsigned loc1 = loc0 + 400 * 4;                                    // buf1
    unsigned rem0, rem1, rmb0, rmb1;
    asm("mapa.shared::cluster.u32 %0, %1, %2;" : "=r"(rem0) : "r"(loc0), "r"(peer));
    asm("mapa.shared::cluster.u32 %0, %1, %2;" : "=r"(rem1) : "r"(loc1), "r"(peer));
    asm("mapa.shared::cluster.u32 %0, %1, %2;" : "=r"(rmb0) : "r"(mb0),  "r"(peer));
    asm("mapa.shared::cluster.u32 %0, %1, %2;" : "=r"(rmb1) : "r"(mb1),  "r"(peer));

    asm volatile("barrier.cluster.arrive.aligned;" ::: "memory");
    asm volatile("barrier.cluster.wait.aligned;"   ::: "memory");

    const float* xwp = g_xw + (size_t)dir * SQ * G4 + (size_t)cta * 96 + rr;
    const unsigned* prog = g_prog + dir * 64;
    int bmark = dir ? 63 : 0;            // (tn & 63) value at a new-row boundary

    float c_reg = 0.0f;
    float xw_cur = 0.0f;
    if (q == 0) {
        prog_poll(prog + (dir ? 63 : 0));                    // initial row ready?
        xw_cur = __ldcg(xwp + (size_t)(dir ? SQ - 1 : 0) * G4);
    }
    unsigned ph0 = 0, ph1 = 0;

    for (int t = 0; t < SQ; t++) {
        int par = t & 1;

        // prefetch next step's xw (poll its row first at boundaries)
        float xw_next = 0.0f;
        if (q == 0 && t + 1 < SQ) {
            int tn = dir ? (SQ - 2 - t) : (t + 1);
            if ((tn & 63) == bmark) prog_poll(prog + (tn >> 6));
            xw_next = __ldcg(xwp + (size_t)tn * G4);
        }

        // wait for this step's h buffer (t=0 consumes zeros)
        if (t > 0) {
            if (par) { mbar_wait(mb1, ph1); ph1 ^= 1; if (tid == 0) mbar_expect(mb1, 1536); }
            else     { mbar_wait(mb0, ph0); ph0 ^= 1; if (tid == 0) mbar_expect(mb0, 1536); }
        }

        // MAC: row rr, k-chunk q
        const ulonglong2* hp2 =
            reinterpret_cast<const ulonglong2*>(sh_h + par * 400 + q * 100);
        ull a0 = 0ull, a1 = 0ull, a2 = 0ull, a3 = 0ull;
        #pragma unroll
        for (int j = 0; j < 12; j++) {
            ulonglong2 x0 = hp2[2 * j];
            ulonglong2 x1 = hp2[2 * j + 1];
            asm("fma.rn.f32x2 %0, %1, %2, %0;" : "+l"(a0) : "l"(wreg[4*j+0]), "l"(x0.x));
            asm("fma.rn.f32x2 %0, %1, %2, %0;" : "+l"(a1) : "l"(wreg[4*j+1]), "l"(x0.y));
            asm("fma.rn.f32x2 %0, %1, %2, %0;" : "+l"(a2) : "l"(wreg[4*j+2]), "l"(x1.x));
            asm("fma.rn.f32x2 %0, %1, %2, %0;" : "+l"(a3) : "l"(wreg[4*j+3]), "l"(x1.y));
        }
        asm("add.rn.f32x2 %0, %0, %1;" : "+l"(a0) : "l"(a1));
        asm("add.rn.f32x2 %0, %0, %1;" : "+l"(a2) : "l"(a3));
        asm("add.rn.f32x2 %0, %0, %1;" : "+l"(a0) : "l"(a2));
        float lo, hi;
        asm("mov.b64 {%0, %1}, %2;" : "=f"(lo), "=f"(hi) : "l"(a0));
        float s = lo + hi;
        s += __shfl_xor_sync(0xffffffffu, s, 1);
        s += __shfl_xor_sync(0xffffffffu, s, 2);
        if (q == 0) sh_gate[par][rr] = s + xw_cur;
        __syncthreads();   // orders ALL h/gate reads before any push below

        // activation (replicated across the 16 peer-groups, deterministic)
        float gi = sh_gate[par][u],      gf = sh_gate[par][24 + u];
        float gg = sh_gate[par][48 + u], go = sh_gate[par][72 + u];
        float cf = sig_mufu(gf) * c_reg + sig_mufu(gi) * tanh_mufu(gg);
        c_reg = cf;
        float hv = sig_mufu(go) * tanh_mufu(cf);

        // push my unit's h into peer's buf[1-par] IMMEDIATELY (critical path)
        if (t + 1 < SQ) {
            unsigned rem = par ? rem0 : rem1;
            unsigned rmb = par ? rmb0 : rmb1;
            asm volatile("st.async.shared::cluster.mbarrier::complete_tx::bytes.b32 [%0], %1, [%2];"
                         :: "r"(rem), "r"(__float_as_uint(hv)), "r"(rmb) : "memory");
        }

        if (peer == 0) {
            int tt = dir ? (SQ - 1 - t) : t;
            g_tok[(size_t)tt * DIM + dir * HID + hidx] = hv;
        }

        xw_cur = xw_next;
    }

    asm volatile("barrier.cluster.arrive.aligned;" ::: "memory");
    asm volatile("barrier.cluster.wait.aligned;"   ::: "memory");
}

// ---------------------------------------------------------------------------
// Fused kernel: blocks 0..31 = LSTM (2 clusters of 16, wave-1 resident);
// blocks 32..3103 = GEMM tiles on the remaining SMs, overlapped with the
// recurrence via g_prog readiness counters.
// ---------------------------------------------------------------------------
__global__ __launch_bounds__(384, 1) void fused_kernel(
    const float* __restrict__ X,
    const float* __restrict__ Wihf, const float* __restrict__ Wihb,
    const float* __restrict__ bihf, const float* __restrict__ bhhf,
    const float* __restrict__ bihb, const float* __restrict__ bhhb,
    const float* __restrict__ Whh_f, const float* __restrict__ Whh_b)
{
    if (blockIdx.x < 32) {
        lstm_body(Whh_f, Whh_b);
    } else {
        gemm_tile_body(blockIdx.x - 32, threadIdx.x,
                       X, Wihf, Wihb, bihf, bhhf, bihb, bhhb);
    }
}

// ---------------------------------------------------------------------------
// Event mean-pool: one CTA per event
// ---------------------------------------------------------------------------
__global__ __launch_bounds__(256) void pool_kernel(const int* __restrict__ label_event)
{
    int e = blockIdx.x;
    int start = label_event[e * 3 + 0];
    int end   = label_event[e * 3 + 1];
    float inv = 1.0f / (float)(end - start);
    for (int c = threadIdx.x; c < DIM; c += 256) {
        float s = 0.0f;
        for (int r = start; r < end; r++) s += g_tok[(size_t)r * DIM + c];
        g_emb[(size_t)e * DIM + c] = s * inv;
    }
}

// ---------------------------------------------------------------------------
// MLP layer 1: hid = relu(emb @ W1^T + b1)   [1024 x 768] x [768 x 768]
// ---------------------------------------------------------------------------
__global__ __launch_bounds__(256) void gemm_mlp1_kernel(
    const float* __restrict__ W1, const float* __restrict__ b1)
{
    __shared__ float As[32][72];
    __shared__ float Bs[32][72];

    int tid = threadIdx.x;
    int bx = blockIdx.x, by = blockIdx.y;
    int tx = tid & 15, ty = tid >> 4;

    ull acc2[4][2];
    #pragma unroll
    for (int i = 0; i < 4; i++) { acc2[i][0] = 0ull; acc2[i][1] = 0ull; }

    for (int k0 = 0; k0 < DIM; k0 += 32) {
        #pragma unroll
        for (int i = 0; i < 2; i++) {
            int id = tid + i * 256;
            int r = id >> 3, c4 = id & 7;
            float4 v = *reinterpret_cast<const float4*>(g_emb + (size_t)(by * 64 + r) * DIM + k0 + c4 * 4);
            As[c4*4+0][r] = v.x; As[c4*4+1][r] = v.y; As[c4*4+2][r] = v.z; As[c4*4+3][r] = v.w;
            float4 w = *reinterpret_cast<const float4*>(W1 + (size_t)(bx * 64 + r) * DIM + k0 + c4 * 4);
            Bs[c4*4+0][r] = w.x; Bs[c4*4+1][r] = w.y; Bs[c4*4+2][r] = w.z; Bs[c4*4+3][r] = w.w;
        }
        __syncthreads();
        #pragma unroll
        for (int k = 0; k < 32; k++) {
            float4 av = *reinterpret_cast<const float4*>(&As[k][ty * 4]);
            ull b0 = *reinterpret_cast<const ull*>(&Bs[k][tx * 4]);
            ull b1v = *reinterpret_cast<const ull*>(&Bs[k][tx * 4 + 2]);
            float a_[4] = {av.x, av.y, av.z, av.w};
            #pragma unroll
            for (int i = 0; i < 4; i++) {
                ull ad;
                asm("mov.b64 %0, {%1, %1};" : "=l"(ad) : "f"(a_[i]));
                asm("fma.rn.f32x2 %0, %1, %2, %0;" : "+l"(acc2[i][0]) : "l"(ad), "l"(b0));
                asm("fma.rn.f32x2 %0, %1, %2, %0;" : "+l"(acc2[i][1]) : "l"(ad), "l"(b1v));
            }
        }
        __syncthreads();
    }

    int col0 = bx * 64 + tx * 4;
    #pragma unroll
    for (int i = 0; i < 4; i++) {
        int row = by * 64 + ty * 4 + i;
        float2 p0 = *reinterpret_cast<float2*>(&acc2[i][0]);
        float2 p1 = *reinterpret_cast<float2*>(&acc2[i][1]);
        float* o = g_hidn + (size_t)row * DIM + col0;
        o[0] = fmaxf(p0.x + b1[col0 + 0], 0.0f);
        o[1] = fmaxf(p0.y + b1[col0 + 1], 0.0f);
        o[2] = fmaxf(p1.x + b1[col0 + 2], 0.0f);
        o[3] = fmaxf(p1.y + b1[col0 + 3], 0.0f);
    }
}

// ---------------------------------------------------------------------------
// Layer 2 + log-softmax + weighted CE per event. One warp per event.
// ---------------------------------------------------------------------------
__global__ __launch_bounds__(256) void scores_kernel(
    const float* __restrict__ W2, const float* __restrict__ b2,
    const int* __restrict__ label_event, float* scores_out)
{
    int lane = threadIdx.x & 31;
    int w = threadIdx.x >> 5;
    int e = blockIdx.x * 8 + w;
    const float* hrow = g_hidn + (size_t)e * DIM;

    float s0 = 0.0f, s1 = 0.0f;
    #pragma unroll
    for (int k = 0; k < 24; k++) {
        float v = hrow[lane + 32 * k];
        s0 += v * __ldg(&W2[lane + 32 * k]);
        s1 += v * __ldg(&W2[DIM + lane + 32 * k]);
    }
    #pragma unroll
    for (int m = 16; m >= 1; m >>= 1) {
        s0 += __shfl_xor_sync(0xffffffffu, s0, m);
        s1 += __shfl_xor_sync(0xffffffffu, s1, m);
    }
    if (lane == 0) {
        s0 += b2[0]; s1 += b2[1];
        float* sp = scores_out ? scores_out : g_scores_scratch;
        sp[2 * e + 0] = s0;
        sp[2 * e + 1] = s1;
        float mx = fmaxf(s0, s1);
        float lse = mx + logf(expf(s0 - mx) + expf(s1 - mx));
        int lab = label_event[e * 3 + 2];
        float sl = lab ? s1 : s0;
        float ce = lse - sl;
        float wgt = (lab == 0) ? 1.0f : (float)lab * 1.0f;
        g_evloss[e] = ce * wgt;
    }
}

__global__ __launch_bounds__(1024) void loss_reduce_kernel(float* loss_out)
{
    __shared__ float red[1024];
    int tid = threadIdx.x;
    red[tid] = g_evloss[tid];
    __syncthreads();
    for (int s = 512; s >= 1; s >>= 1) {
        if (tid < s) red[tid] += red[tid + s];
        __syncthreads();
    }
    if (tid == 0) {
        float* lp = loss_out ? loss_out : g_loss_scratch;
        lp[0] = red[0];
    }
}

// ---------------------------------------------------------------------------
extern "C" void kernel_launch(void* const* d_in, const int* in_sizes, int n_in,
                              void* d_out, int out_size) {
    const float* X     = (const float*)d_in[0];
    const int*   lev   = (const int*)  d_in[1];
    const float* Wih_f = (const float*)d_in[2];
    const float* Whh_f = (const float*)d_in[3];
    const float* bih_f = (const float*)d_in[4];
    const float* bhh_f = (const float*)d_in[5];
    const float* Wih_b = (const float*)d_in[6];
    const float* Whh_b = (const float*)d_in[7];
    const float* bih_b = (const float*)d_in[8];
    const float* bhh_b = (const float*)d_in[9];
    const float* W1    = (const float*)d_in[10];
    const float* b1    = (const float*)d_in[11];
    const float* W2    = (const float*)d_in[12];
    const float* b2    = (const float*)d_in[13];

    float* out = (float*)d_out;
    float* loss_ptr   = nullptr;
    float* scores_ptr = nullptr;
    if (out_size >= 2049)      { loss_ptr = out; scores_ptr = out + 1; }
    else if (out_size >= 2048) { scores_ptr = out; }
    else                       { loss_ptr = out; }

    init_kernel<<<1, 128>>>();
    dummy_kernel<<<1, 32>>>();
    dummy_kernel<<<1, 32>>>();

    // Fused LSTM (blocks 0..31, 2x16-CTA clusters) + overlapped GEMM tiles
    cudaFuncSetAttribute((const void*)fused_kernel,
                         cudaFuncAttributeNonPortableClusterSizeAllowed, 1);
    cudaLaunchConfig_t cfg = {};
    cfg.gridDim  = dim3(32 + 64 * 48, 1, 1);     // 3104 = 16 * 194
    cfg.blockDim = dim3(384, 1, 1);
    cfg.dynamicSmemBytes = 0;
    cudaLaunchAttribute attrs[1];
    attrs[0].id = cudaLaunchAttributeClusterDimension;
    attrs[0].val.clusterDim.x = 16;
    attrs[0].val.clusterDim.y = 1;
    attrs[0].val.clusterDim.z = 1;
    cfg.attrs = attrs;
    cfg.numAttrs = 1;
    cudaLaunchKernelEx(&cfg, fused_kernel,
                       X, Wih_f, Wih_b, bih_f, bhh_f, bih_b, bhh_b,
                       Whh_f, Whh_b);

    pool_kernel<<<NEV, 256>>>(lev);
    gemm_mlp1_kernel<<<dim3(12, 16), 256>>>(W1, b1);
    scores_kernel<<<NEV / 8, 256>>>(W2, b2, lev, scores_ptr);
    loss_reduce_kernel<<<1, 1024>>>(loss_ptr);
}